// round 1
// baseline (speedup 1.0000x reference)
#include <cuda_runtime.h>
#include <cstdint>

#define NT 512
constexpr int Tn  = 16;
constexpr int Bn  = 16;
constexpr int Nn  = 1024;
constexpr int En  = 16384;
constexpr int Fin = 128;
constexpr int Hn  = 256;
constexpr int Kn  = 820;
constexpr int NG  = Tn * Bn;   // 256 graphs

// ---------------- global scratch (no allocations allowed) ----------------
__device__ float    g_emb[NG * Hn];          // [256][256]
__device__ float    g_ihpre[NG * 4 * Hn];    // [256][1024]  x@W_ih^T + b_ih + b_hh
__device__ float    g_h[Bn * Hn];            // LSTM hidden state [16][256]
__device__ unsigned g_barc;                  // grid spin-barrier counter

__device__ __forceinline__ float sigmoidf_(float v) { return 1.0f / (1.0f + expf(-v)); }

// =====================================================================
// K1: per-graph embedding. One CTA per graph, everything in SMEM.
// =====================================================================
__global__ __launch_bounds__(NT) void k_embed(
    const float* __restrict__ x, const int* __restrict__ ei,
    const float* __restrict__ W1, const float* __restrict__ b1,
    const float* __restrict__ Wl, const float* __restrict__ Wr,
    const float* __restrict__ sb,
    const float* __restrict__ W2, const float* __restrict__ b2)
{
    extern __shared__ float sm[];
    float* A     = sm;                 // 16384 : h / h1 / pre
    float* Bf    = A + Nn * 16;        // 16384 : agg / aggs / xp
    float* dinv  = Bf + Nn * 16;       // 1024
    float* score = dinv + Nn;          // 1024
    unsigned long long* keys = (unsigned long long*)(score + Nn); // 1024 u64
    int*   newidx = (int*)(keys + Nn);                            // 1024
    float* dinv2  = (float*)(newidx + Nn);                        // 1024
    float* w1s    = dinv2 + Nn;        // 2048
    float* w2s    = w1s + Fin * 16;    // 4096
    float* b2s    = w2s + 16 * Hn;     // 256
    float* cst    = b2s + Hn;          // 64 : [0..15]=b1 [16..31]=Wl [32..47]=Wr [48]=sag_b
    float* red    = cst + 64;          // 256

    const int tid = threadIdx.x;
    const int g   = blockIdx.x;
    const float* xg   = x  + (size_t)g * Nn * Fin;
    const int*   srcp = ei + (size_t)g * 2 * En;
    const int*   dstp = srcp + En;

    for (int i = tid; i < Fin * 16; i += NT) w1s[i] = W1[i];
    for (int i = tid; i < 16 * Hn;  i += NT) w2s[i] = W2[i];
    for (int i = tid; i < Hn;       i += NT) b2s[i] = b2[i];
    if (tid < 16) { cst[tid] = b1[tid]; cst[16 + tid] = Wl[tid]; cst[32 + tid] = Wr[tid]; }
    if (tid == 0) cst[48] = sb[0];
    for (int i = tid; i < Nn;      i += NT) dinv[i] = 1.0f;
    for (int i = tid; i < Nn * 16; i += NT) Bf[i]   = 0.0f;
    __syncthreads();

    // --- degree (conv1): deg = 1 + indegree --------------------------------
    for (int e = tid; e < En; e += NT) atomicAdd(&dinv[dstp[e]], 1.0f);

    // --- conv1 matmul: A = x @ W1  [1024,128]x[128,16] ----------------------
    {
        const int mq = tid & 3;         // which group of 4 output channels
        const int nb = tid >> 2;        // node within wave of 128
        for (int n = nb; n < Nn; n += NT / 4) {
            float a0 = 0.f, a1 = 0.f, a2 = 0.f, a3 = 0.f;
            const float4* xr = (const float4*)(xg + (size_t)n * Fin);
            #pragma unroll
            for (int f4 = 0; f4 < Fin / 4; f4++) {
                float4 xv = xr[f4];
                const int fb = f4 * 4;
                float4 q0 = *(const float4*)&w1s[(fb + 0) * 16 + mq * 4];
                float4 q1 = *(const float4*)&w1s[(fb + 1) * 16 + mq * 4];
                float4 q2 = *(const float4*)&w1s[(fb + 2) * 16 + mq * 4];
                float4 q3 = *(const float4*)&w1s[(fb + 3) * 16 + mq * 4];
                a0 += xv.x * q0.x + xv.y * q1.x + xv.z * q2.x + xv.w * q3.x;
                a1 += xv.x * q0.y + xv.y * q1.y + xv.z * q2.y + xv.w * q3.y;
                a2 += xv.x * q0.z + xv.y * q1.z + xv.z * q2.z + xv.w * q3.z;
                a3 += xv.x * q0.w + xv.y * q1.w + xv.z * q2.w + xv.w * q3.w;
            }
            *(float4*)&A[n * 16 + mq * 4] = make_float4(a0, a1, a2, a3);
        }
    }
    __syncthreads();
    for (int i = tid; i < Nn; i += NT) dinv[i] = rsqrtf(dinv[i]);
    __syncthreads();

    // --- conv1 scatter: Bf[d] += A[s] * dinv[s]*dinv[d] ----------------------
    for (int e = tid; e < En; e += NT) {
        const int s = srcp[e], d = dstp[e];
        const float coef = dinv[s] * dinv[d];
        const float* hsrc = &A[s * 16];
        float* bd = &Bf[d * 16];
        #pragma unroll
        for (int m = 0; m < 16; m++) atomicAdd(&bd[m], hsrc[m] * coef);
    }
    __syncthreads();

    // --- h1 = relu(Bf + A*dinv^2 + b1) -> A ---------------------------------
    for (int i = tid; i < Nn * 16; i += NT) {
        const int n = i >> 4, m = i & 15;
        const float di = dinv[n];
        const float v = Bf[i] + A[i] * (di * di) + cst[m];
        A[i] = v > 0.f ? v : 0.f;
    }
    __syncthreads();
    for (int i = tid; i < Nn * 16; i += NT) Bf[i] = 0.0f;
    __syncthreads();

    // --- SAG aggregate: Bf[d] += h1[s] --------------------------------------
    for (int e = tid; e < En; e += NT) {
        const int s = srcp[e], d = dstp[e];
        const float* hsrc = &A[s * 16];
        float* bd = &Bf[d * 16];
        #pragma unroll
        for (int m = 0; m < 16; m++) atomicAdd(&bd[m], hsrc[m]);
    }
    __syncthreads();

    // --- score + sortable key ------------------------------------------------
    for (int n = tid; n < Nn; n += NT) {
        float sc = cst[48];
        #pragma unroll
        for (int m = 0; m < 16; m++)
            sc += Bf[n * 16 + m] * cst[16 + m] + A[n * 16 + m] * cst[32 + m];
        score[n] = sc;
        unsigned u = __float_as_uint(sc);
        u = (u & 0x80000000u) ? ~u : (u | 0x80000000u);   // ascending-sortable float
        keys[n] = ((unsigned long long)(~u) << 32) | (unsigned)n; // asc key = desc score, tie -> low idx
    }
    __syncthreads();

    // --- bitonic sort (ascending), 1024 keys, 512 threads --------------------
    for (int k = 2; k <= Nn; k <<= 1) {
        for (int j = k >> 1; j > 0; j >>= 1) {
            const int i  = tid;
            const int lo = ((i & ~(j - 1)) << 1) | (i & (j - 1));
            const int hi = lo + j;
            const unsigned long long a = keys[lo], b = keys[hi];
            const bool up = ((lo & k) == 0);
            if (up ? (a > b) : (a < b)) { keys[lo] = b; keys[hi] = a; }
            __syncthreads();
        }
    }

    // --- build newidx, gate kept nodes into Bf (xp) ---------------------------
    for (int n = tid; n < Nn; n += NT) newidx[n] = -1;
    __syncthreads();
    for (int r = tid; r < Kn; r += NT)
        newidx[(int)(keys[r] & 0xFFFFFFFFull)] = r;
    __syncthreads();
    for (int i = tid; i < Kn * 16; i += NT) {
        const int r = i >> 4, m = i & 15;
        const int n = (int)(keys[r] & 0xFFFFFFFFull);
        Bf[i] = A[n * 16 + m] * tanhf(score[n]);
    }
    for (int r = tid; r < Kn; r += NT) dinv2[r] = 1.0f;
    __syncthreads();

    // --- deg2 over valid remapped edges ---------------------------------------
    for (int e = tid; e < En; e += NT) {
        const int ns = newidx[srcp[e]], nd = newidx[dstp[e]];
        if ((ns | nd) >= 0) atomicAdd(&dinv2[nd], 1.0f);
    }
    __syncthreads();
    for (int r = tid; r < Kn; r += NT) dinv2[r] = rsqrtf(dinv2[r]);
    __syncthreads();

    // --- conv2 pre-aggregation in MID space: A = self + scatter ---------------
    for (int i = tid; i < Kn * 16; i += NT) {
        const int r = i >> 4;
        const float d = dinv2[r];
        A[i] = Bf[i] * (d * d);
    }
    __syncthreads();
    for (int e = tid; e < En; e += NT) {
        const int ns = newidx[srcp[e]], nd = newidx[dstp[e]];
        if ((ns | nd) >= 0) {
            const float coef = dinv2[ns] * dinv2[nd];
            const float* xs = &Bf[ns * 16];
            float* pd = &A[nd * 16];
            #pragma unroll
            for (int m = 0; m < 16; m++) atomicAdd(&pd[m], xs[m] * coef);
        }
    }
    __syncthreads();

    // --- h2 = relu(pre @ W2 + b2), mean over K -> g_emb -----------------------
    {
        const int c    = tid & 255;
        const int half = tid >> 8;
        float wc[16];
        #pragma unroll
        for (int m = 0; m < 16; m++) wc[m] = w2s[m * Hn + c];
        const float bias = b2s[c];
        float acc = 0.f;
        for (int r = half; r < Kn; r += 2) {
            const float4* pr4 = (const float4*)&A[r * 16];
            float4 p0 = pr4[0], p1 = pr4[1], p2 = pr4[2], p3 = pr4[3];
            float v = bias
                + p0.x * wc[0]  + p0.y * wc[1]  + p0.z * wc[2]  + p0.w * wc[3]
                + p1.x * wc[4]  + p1.y * wc[5]  + p1.z * wc[6]  + p1.w * wc[7]
                + p2.x * wc[8]  + p2.y * wc[9]  + p2.z * wc[10] + p2.w * wc[11]
                + p3.x * wc[12] + p3.y * wc[13] + p3.z * wc[14] + p3.w * wc[15];
            acc += v > 0.f ? v : 0.f;
        }
        if (half == 1) red[c] = acc;
        __syncthreads();
        if (half == 0) g_emb[(size_t)g * Hn + c] = (acc + red[c]) * (1.0f / (float)Kn);
    }
}

// =====================================================================
// K2: ih_pre = emb @ W_ih^T + b_ih + b_hh ; reset LSTM state + barrier
// =====================================================================
__global__ __launch_bounds__(256) void k_prep(
    const float* __restrict__ W_ih, const float* __restrict__ b_ih,
    const float* __restrict__ b_hh)
{
    __shared__ float es[Hn];
    const int tid = threadIdx.x, g = blockIdx.x;
    es[tid] = g_emb[(size_t)g * Hn + tid];
    __syncthreads();
    const int warp = tid >> 5, lane = tid & 31;
    for (int j = warp; j < 4 * Hn; j += 8) {
        const float* wr = W_ih + (size_t)j * Hn;
        float p = 0.f;
        #pragma unroll 4
        for (int k = lane; k < Hn; k += 32) p += wr[k] * es[k];
        #pragma unroll
        for (int o = 16; o; o >>= 1) p += __shfl_xor_sync(0xFFFFFFFFu, p, o);
        if (lane == 0) g_ihpre[(size_t)g * (4 * Hn) + j] = p + b_ih[j] + b_hh[j];
    }
    if (g == 0) {
        for (int i = tid; i < Bn * Hn; i += 256) g_h[i] = 0.f;
        if (tid == 0) g_barc = 0u;
    }
}

// =====================================================================
// K3: persistent LSTM (64 CTAs, all co-resident) + classifier.
// CTA m owns hidden units [4m,4m+4) x 4 gates x all 16 batches.
// =====================================================================
__global__ __launch_bounds__(256) void k_lstm(
    const float* __restrict__ W_hh, const float* __restrict__ cls_W,
    const float* __restrict__ cls_b, float* __restrict__ out)
{
    __shared__ float Ws[Hn * 16];    // [k][q]  W_hh slice, resident all steps
    __shared__ float hs[Hn * 17];    // [k][b]  padded stride 17
    __shared__ float gsm[256];
    __shared__ float cs[64];
    __shared__ float red[256];
    const int tid = threadIdx.x;
    const int m   = blockIdx.x;      // 0..63

    for (int idx = tid; idx < 16 * Hn; idx += 256) {
        const int q = idx >> 8;            // 0..15
        const int k = idx & 255;
        const int hu_l = q >> 2, gate = q & 3;
        const int j = gate * Hn + (m * 4 + hu_l);
        Ws[k * 16 + q] = W_hh[(size_t)j * Hn + k];  // coalesced row reads
    }
    if (tid < 64) cs[tid] = 0.f;
    __syncthreads();

    const int b = tid & 15, q = tid >> 4;
    const int hu_l = q >> 2, gate = q & 3;
    const int j = gate * Hn + (m * 4 + hu_l);

    for (int t = 0; t < Tn; t++) {
        // stage h (bypass L1: cross-CTA writes within this kernel)
        for (int idx = tid; idx < Bn * Hn; idx += 256) {
            const int bb = idx >> 8, kk = idx & 255;
            hs[kk * 17 + bb] = __ldcg(&g_h[idx]);
        }
        __syncthreads();

        float acc = g_ihpre[(size_t)(t * Bn + b) * (4 * Hn) + j];
        #pragma unroll 8
        for (int k = 0; k < Hn; k++) acc += Ws[k * 16 + q] * hs[k * 17 + b];
        gsm[b * 16 + q] = acc;
        __syncthreads();

        if (tid < 64) {
            const int bb = tid & 15, hl = tid >> 4;
            const float gi = gsm[bb * 16 + hl * 4 + 0];
            const float gf = gsm[bb * 16 + hl * 4 + 1];
            const float gg = gsm[bb * 16 + hl * 4 + 2];
            const float go = gsm[bb * 16 + hl * 4 + 3];
            float cc = cs[tid];
            cc = sigmoidf_(gf) * cc + sigmoidf_(gi) * tanhf(gg);
            cs[tid] = cc;
            __stcg(&g_h[bb * Hn + (m * 4 + hl)], sigmoidf_(go) * tanhf(cc));
        }
        __syncthreads();

        // grid spin-barrier (64 co-resident CTAs; counter reset by K2 each replay)
        if (tid == 0) {
            __threadfence();
            atomicAdd(&g_barc, 1u);
            const unsigned target = 64u * (unsigned)(t + 1);
            unsigned v;
            do {
                asm volatile("ld.global.acquire.gpu.u32 %0, [%1];" : "=r"(v) : "l"(&g_barc));
                if (v < target) __nanosleep(64);
            } while (v < target);
        }
        __syncthreads();
    }

    // classifier on CTA 0: out[b] = h_T[b] . cls_W + cls_b
    if (m == 0) {
        const float w = cls_W[tid];
        for (int bb = 0; bb < Bn; bb++) {
            red[tid] = __ldcg(&g_h[bb * Hn + tid]) * w;
            __syncthreads();
            for (int off = 128; off; off >>= 1) {
                if (tid < off) red[tid] += red[tid + off];
                __syncthreads();
            }
            if (tid == 0) out[bb] = red[0] + cls_b[0];
            __syncthreads();
        }
    }
}

// =====================================================================
extern "C" void kernel_launch(void* const* d_in, const int* in_sizes, int n_in,
                              void* d_out, int out_size)
{
    (void)in_sizes; (void)n_in; (void)out_size;
    const float* x     = (const float*)d_in[0];
    const int*   ei    = (const int*)  d_in[1];
    const float* W1    = (const float*)d_in[2];
    const float* b1    = (const float*)d_in[3];
    const float* Wl    = (const float*)d_in[4];
    const float* Wr    = (const float*)d_in[5];
    const float* sb    = (const float*)d_in[6];
    const float* W2    = (const float*)d_in[7];
    const float* b2    = (const float*)d_in[8];
    const float* W_ih  = (const float*)d_in[9];
    const float* W_hh  = (const float*)d_in[10];
    const float* b_ih  = (const float*)d_in[11];
    const float* b_hh  = (const float*)d_in[12];
    const float* cls_W = (const float*)d_in[13];
    const float* cls_b = (const float*)d_in[14];
    float* out = (float*)d_out;

    const size_t smem = 45632 * sizeof(float);  // 182528 B
    cudaFuncSetAttribute(k_embed, cudaFuncAttributeMaxDynamicSharedMemorySize, (int)smem);

    k_embed<<<NG, NT, smem>>>(x, ei, W1, b1, Wl, Wr, sb, W2, b2);
    k_prep <<<NG, 256>>>(W_ih, b_ih, b_hh);
    k_lstm <<<64, 256>>>(W_hh, cls_W, cls_b, out);
}

// round 2
// speedup vs baseline: 4.0097x; 4.0097x over previous
#include <cuda_runtime.h>
#include <cstdint>

#define NT 512
constexpr int Tn  = 16;
constexpr int Bn  = 16;
constexpr int Nn  = 1024;
constexpr int En  = 16384;
constexpr int Fin = 128;
constexpr int Hn  = 256;
constexpr int Kn  = 820;
constexpr int NG  = Tn * Bn;   // 256 graphs

// ---------------- global scratch (no allocations allowed) ----------------
__device__ float    g_emb[NG * Hn];
__device__ float    g_ihpre[NG * 4 * Hn];
__device__ float    g_h[Bn * Hn];
__device__ unsigned g_barc;

__device__ __forceinline__ float sigmoidf_(float v) { return 1.0f / (1.0f + expf(-v)); }

// =====================================================================
// K1: per-graph embedding. One CTA per graph. CSR (counting sort by dst)
// built once in SMEM; all aggregations are atomic-free gather/reduce.
// =====================================================================
__global__ __launch_bounds__(NT) void k_embed(
    const float* __restrict__ x, const int* __restrict__ ei,
    const float* __restrict__ W1, const float* __restrict__ b1,
    const float* __restrict__ Wl, const float* __restrict__ Wr,
    const float* __restrict__ sb,
    const float* __restrict__ W2, const float* __restrict__ b2)
{
    extern __shared__ float sm[];
    // all bases multiples of 4 floats (16B) for float4 access
    float*              A      = sm;                                   // 16384
    float*              Bf     = sm + 16384;                           // 16384
    unsigned long long* keys   = (unsigned long long*)(sm + 32768);    // 1024 u64
    unsigned short*     srcs   = (unsigned short*)(sm + 34816);        // 16384 u16
    int*                off    = (int*)(sm + 43008);                   // 1025 (+pad)
    int*                cur    = (int*)(sm + 44036);                   // 1024
    float*              dinv   = sm + 45060;                           // 1024
    float*              score  = sm + 46084;                           // 1024
    int*                newidx = (int*)(sm + 47108);                   // 1024
    float*              dinv2  = sm + 48132;                           // 1024
    float*              w1s    = sm + 49156;                           // 2048
    float*              w2s    = sm + 51204;                           // 4096
    float*              b2s    = sm + 55300;                           // 256
    float*              cst    = sm + 55556;                           // 64
    float*              red    = sm + 55620;                           // 256

    const int tid = threadIdx.x;
    const int g   = blockIdx.x;
    const float* xg   = x  + (size_t)g * Nn * Fin;
    const int*   srcp = ei + (size_t)g * 2 * En;
    const int*   dstp = srcp + En;

    // --- preload weights, zero histogram -----------------------------------
    for (int i = tid; i < Fin * 16; i += NT) w1s[i] = W1[i];
    for (int i = tid; i < 16 * Hn;  i += NT) w2s[i] = W2[i];
    for (int i = tid; i < Hn;       i += NT) b2s[i] = b2[i];
    if (tid < 16) { cst[tid] = b1[tid]; cst[16 + tid] = Wl[tid]; cst[32 + tid] = Wr[tid]; }
    if (tid == 0) cst[48] = sb[0];
    for (int i = tid; i < Nn; i += NT) cur[i] = 0;
    __syncthreads();

    // --- histogram of dst (int atomics; also gives conv1 degree) -----------
    for (int e = tid; e < En; e += NT) atomicAdd(&cur[dstp[e]], 1);

    // --- conv1 matmul: A = x @ W1  [1024,128]x[128,16] (overlaps histogram)
    {
        const int mq = tid & 3;
        const int nb = tid >> 2;
        for (int n = nb; n < Nn; n += NT / 4) {
            float a0 = 0.f, a1 = 0.f, a2 = 0.f, a3 = 0.f;
            const float4* xr = (const float4*)(xg + (size_t)n * Fin);
            #pragma unroll
            for (int f4 = 0; f4 < Fin / 4; f4++) {
                float4 xv = xr[f4];
                const int fb = f4 * 4;
                float4 q0 = *(const float4*)&w1s[(fb + 0) * 16 + mq * 4];
                float4 q1 = *(const float4*)&w1s[(fb + 1) * 16 + mq * 4];
                float4 q2 = *(const float4*)&w1s[(fb + 2) * 16 + mq * 4];
                float4 q3 = *(const float4*)&w1s[(fb + 3) * 16 + mq * 4];
                a0 += xv.x * q0.x + xv.y * q1.x + xv.z * q2.x + xv.w * q3.x;
                a1 += xv.x * q0.y + xv.y * q1.y + xv.z * q2.y + xv.w * q3.y;
                a2 += xv.x * q0.z + xv.y * q1.z + xv.z * q2.z + xv.w * q3.z;
                a3 += xv.x * q0.w + xv.y * q1.w + xv.z * q2.w + xv.w * q3.w;
            }
            *(float4*)&A[n * 16 + mq * 4] = make_float4(a0, a1, a2, a3);
        }
    }
    __syncthreads();

    // --- exclusive Blelloch scan of counts -> off[0..1024] -----------------
    for (int i = tid; i < Nn; i += NT) off[i] = cur[i];
    for (int d2 = 1; d2 < Nn; d2 <<= 1) {
        __syncthreads();
        const int idx = (tid + 1) * (d2 << 1) - 1;
        if (idx < Nn) off[idx] += off[idx - d2];
    }
    __syncthreads();
    if (tid == 0) { off[Nn] = off[Nn - 1]; off[Nn - 1] = 0; }
    for (int d2 = Nn >> 1; d2 >= 1; d2 >>= 1) {
        __syncthreads();
        const int idx = (tid + 1) * (d2 << 1) - 1;
        if (idx < Nn) { const int t = off[idx - d2]; off[idx - d2] = off[idx]; off[idx] += t; }
    }
    __syncthreads();

    // --- cur = running cursor; dinv from degree -----------------------------
    for (int i = tid; i < Nn; i += NT) {
        cur[i]  = off[i];
        dinv[i] = rsqrtf(1.0f + (float)(off[i + 1] - off[i]));
    }
    __syncthreads();

    // --- placement: srcs sorted by dst (int atomics on cursors) ------------
    for (int e = tid; e < En; e += NT) {
        const int pos = atomicAdd(&cur[dstp[e]], 1);
        srcs[pos] = (unsigned short)srcp[e];
    }
    __syncthreads();

    // --- conv1 gather + self + bias + relu -> Bf = h1 -----------------------
    {
        const int grp = tid >> 2, q = tid & 3;
        const float bx = cst[q * 4 + 0], by = cst[q * 4 + 1];
        const float bz = cst[q * 4 + 2], bw = cst[q * 4 + 3];
        for (int d = grp; d < Nn; d += NT / 4) {
            const int e0 = off[d], e1 = off[d + 1];
            float ax = 0.f, ay = 0.f, az = 0.f, aw = 0.f;
            for (int j = e0; j < e1; j++) {
                const int s = srcs[j];
                const float w = dinv[s];
                const float4 v = *(const float4*)&A[s * 16 + q * 4];
                ax = fmaf(v.x, w, ax); ay = fmaf(v.y, w, ay);
                az = fmaf(v.z, w, az); aw = fmaf(v.w, w, aw);
            }
            const float dd = dinv[d], dd2 = dd * dd;
            const float4 sv = *(const float4*)&A[d * 16 + q * 4];
            float4 o;
            o.x = fmaxf(fmaf(ax, dd, fmaf(sv.x, dd2, bx)), 0.f);
            o.y = fmaxf(fmaf(ay, dd, fmaf(sv.y, dd2, by)), 0.f);
            o.z = fmaxf(fmaf(az, dd, fmaf(sv.z, dd2, bz)), 0.f);
            o.w = fmaxf(fmaf(aw, dd, fmaf(sv.w, dd2, bw)), 0.f);
            *(float4*)&Bf[d * 16 + q * 4] = o;
        }
    }
    __syncthreads();

    // --- SAG aggregate (plain sum of neighbors) -> A = agg -------------------
    {
        const int grp = tid >> 2, q = tid & 3;
        for (int d = grp; d < Nn; d += NT / 4) {
            const int e0 = off[d], e1 = off[d + 1];
            float ax = 0.f, ay = 0.f, az = 0.f, aw = 0.f;
            for (int j = e0; j < e1; j++) {
                const float4 v = *(const float4*)&Bf[srcs[j] * 16 + q * 4];
                ax += v.x; ay += v.y; az += v.z; aw += v.w;
            }
            *(float4*)&A[d * 16 + q * 4] = make_float4(ax, ay, az, aw);
        }
    }
    __syncthreads();

    // --- score + sortable key (A=agg with Wl, Bf=h1 with Wr) -----------------
    for (int n = tid; n < Nn; n += NT) {
        float sc = cst[48];
        #pragma unroll
        for (int m = 0; m < 16; m++)
            sc += A[n * 16 + m] * cst[16 + m] + Bf[n * 16 + m] * cst[32 + m];
        score[n] = sc;
        unsigned u = __float_as_uint(sc);
        u = (u & 0x80000000u) ? ~u : (u | 0x80000000u);
        keys[n] = ((unsigned long long)(~u) << 32) | (unsigned)n;
    }
    __syncthreads();

    // --- bitonic sort (ascending key = descending score, tie -> low idx) -----
    for (int k = 2; k <= Nn; k <<= 1) {
        for (int j = k >> 1; j > 0; j >>= 1) {
            const int i  = tid;
            const int lo = ((i & ~(j - 1)) << 1) | (i & (j - 1));
            const int hi = lo + j;
            const unsigned long long a = keys[lo], b = keys[hi];
            const bool up = ((lo & k) == 0);
            if (up ? (a > b) : (a < b)) { keys[lo] = b; keys[hi] = a; }
            __syncthreads();
        }
    }

    // --- newidx, gated xp -> A rows [0,K) -------------------------------------
    for (int n = tid; n < Nn; n += NT) newidx[n] = -1;
    __syncthreads();
    for (int r = tid; r < Kn; r += NT)
        newidx[(int)(keys[r] & 0xFFFFFFFFull)] = r;
    __syncthreads();
    for (int i = tid; i < Kn * 16; i += NT) {
        const int r = i >> 4, m = i & 15;
        const int n = (int)(keys[r] & 0xFFFFFFFFull);
        A[r * 16 + m] = Bf[n * 16 + m] * tanhf(score[n]);
    }
    __syncthreads();

    // --- deg2: count valid (kept->kept) in-edges per kept node ---------------
    for (int d = tid; d < Nn; d += NT) {
        const int nd = newidx[d];
        if (nd >= 0) {
            int c = 0;
            const int e0 = off[d], e1 = off[d + 1];
            for (int j = e0; j < e1; j++) c += (newidx[srcs[j]] >= 0);
            dinv2[nd] = rsqrtf(1.0f + (float)c);
        }
    }
    __syncthreads();

    // --- conv2 pre-aggregation (MID space) -> Bf rows [0,K) -------------------
    {
        const int grp = tid >> 2, q = tid & 3;
        for (int d = grp; d < Nn; d += NT / 4) {
            const int nd = newidx[d];
            if (nd < 0) continue;
            const int e0 = off[d], e1 = off[d + 1];
            float ax = 0.f, ay = 0.f, az = 0.f, aw = 0.f;
            for (int j = e0; j < e1; j++) {
                const int ns = newidx[srcs[j]];
                if (ns >= 0) {
                    const float w = dinv2[ns];
                    const float4 v = *(const float4*)&A[ns * 16 + q * 4];
                    ax = fmaf(v.x, w, ax); ay = fmaf(v.y, w, ay);
                    az = fmaf(v.z, w, az); aw = fmaf(v.w, w, aw);
                }
            }
            const float dd = dinv2[nd], dd2 = dd * dd;
            const float4 sv = *(const float4*)&A[nd * 16 + q * 4];
            float4 o;
            o.x = fmaf(ax, dd, sv.x * dd2);
            o.y = fmaf(ay, dd, sv.y * dd2);
            o.z = fmaf(az, dd, sv.z * dd2);
            o.w = fmaf(aw, dd, sv.w * dd2);
            *(float4*)&Bf[nd * 16 + q * 4] = o;
        }
    }
    __syncthreads();

    // --- h2 = relu(pre @ W2 + b2), mean over K -> g_emb -----------------------
    {
        const int c    = tid & 255;
        const int half = tid >> 8;
        float wc[16];
        #pragma unroll
        for (int m = 0; m < 16; m++) wc[m] = w2s[m * Hn + c];
        const float bias = b2s[c];
        float acc = 0.f;
        for (int r = half; r < Kn; r += 2) {
            const float4* pr4 = (const float4*)&Bf[r * 16];
            float4 p0 = pr4[0], p1 = pr4[1], p2 = pr4[2], p3 = pr4[3];
            float v = bias
                + p0.x * wc[0]  + p0.y * wc[1]  + p0.z * wc[2]  + p0.w * wc[3]
                + p1.x * wc[4]  + p1.y * wc[5]  + p1.z * wc[6]  + p1.w * wc[7]
                + p2.x * wc[8]  + p2.y * wc[9]  + p2.z * wc[10] + p2.w * wc[11]
                + p3.x * wc[12] + p3.y * wc[13] + p3.z * wc[14] + p3.w * wc[15];
            acc += v > 0.f ? v : 0.f;
        }
        if (half == 1) red[c] = acc;
        __syncthreads();
        if (half == 0) g_emb[(size_t)g * Hn + c] = (acc + red[c]) * (1.0f / (float)Kn);
    }
}

// =====================================================================
// K2: ih_pre = emb @ W_ih^T + b_ih + b_hh ; reset LSTM state + barrier
// =====================================================================
__global__ __launch_bounds__(256) void k_prep(
    const float* __restrict__ W_ih, const float* __restrict__ b_ih,
    const float* __restrict__ b_hh)
{
    __shared__ float es[Hn];
    const int tid = threadIdx.x, g = blockIdx.x;
    es[tid] = g_emb[(size_t)g * Hn + tid];
    __syncthreads();
    const int warp = tid >> 5, lane = tid & 31;
    for (int j = warp; j < 4 * Hn; j += 8) {
        const float* wr = W_ih + (size_t)j * Hn;
        float p = 0.f;
        #pragma unroll 4
        for (int k = lane; k < Hn; k += 32) p += wr[k] * es[k];
        #pragma unroll
        for (int o = 16; o; o >>= 1) p += __shfl_xor_sync(0xFFFFFFFFu, p, o);
        if (lane == 0) g_ihpre[(size_t)g * (4 * Hn) + j] = p + b_ih[j] + b_hh[j];
    }
    if (g == 0) {
        for (int i = tid; i < Bn * Hn; i += 256) g_h[i] = 0.f;
        if (tid == 0) g_barc = 0u;
    }
}

// =====================================================================
// K3: persistent LSTM (64 CTAs, all co-resident) + classifier.
// =====================================================================
__global__ __launch_bounds__(256) void k_lstm(
    const float* __restrict__ W_hh, const float* __restrict__ cls_W,
    const float* __restrict__ cls_b, float* __restrict__ out)
{
    __shared__ float Ws[Hn * 16];
    __shared__ float hs[Hn * 17];
    __shared__ float gsm[256];
    __shared__ float cs[64];
    __shared__ float red[256];
    const int tid = threadIdx.x;
    const int m   = blockIdx.x;

    for (int idx = tid; idx < 16 * Hn; idx += 256) {
        const int q = idx >> 8;
        const int k = idx & 255;
        const int hu_l = q >> 2, gate = q & 3;
        const int j = gate * Hn + (m * 4 + hu_l);
        Ws[k * 16 + q] = W_hh[(size_t)j * Hn + k];
    }
    if (tid < 64) cs[tid] = 0.f;
    __syncthreads();

    const int b = tid & 15, q = tid >> 4;
    const int hu_l = q >> 2, gate = q & 3;
    const int j = gate * Hn + (m * 4 + hu_l);

    for (int t = 0; t < Tn; t++) {
        for (int idx = tid; idx < Bn * Hn; idx += 256) {
            const int bb = idx >> 8, kk = idx & 255;
            hs[kk * 17 + bb] = __ldcg(&g_h[idx]);
        }
        __syncthreads();

        float acc = g_ihpre[(size_t)(t * Bn + b) * (4 * Hn) + j];
        #pragma unroll 8
        for (int k = 0; k < Hn; k++) acc += Ws[k * 16 + q] * hs[k * 17 + b];
        gsm[b * 16 + q] = acc;
        __syncthreads();

        if (tid < 64) {
            const int bb = tid & 15, hl = tid >> 4;
            const float gi = gsm[bb * 16 + hl * 4 + 0];
            const float gf = gsm[bb * 16 + hl * 4 + 1];
            const float gg = gsm[bb * 16 + hl * 4 + 2];
            const float go = gsm[bb * 16 + hl * 4 + 3];
            float cc = cs[tid];
            cc = sigmoidf_(gf) * cc + sigmoidf_(gi) * tanhf(gg);
            cs[tid] = cc;
            __stcg(&g_h[bb * Hn + (m * 4 + hl)], sigmoidf_(go) * tanhf(cc));
        }
        __syncthreads();

        if (tid == 0) {
            __threadfence();
            atomicAdd(&g_barc, 1u);
            const unsigned target = 64u * (unsigned)(t + 1);
            unsigned v;
            do {
                asm volatile("ld.global.acquire.gpu.u32 %0, [%1];" : "=r"(v) : "l"(&g_barc));
                if (v < target) __nanosleep(64);
            } while (v < target);
        }
        __syncthreads();
    }

    if (m == 0) {
        const float w = cls_W[tid];
        for (int bb = 0; bb < Bn; bb++) {
            red[tid] = __ldcg(&g_h[bb * Hn + tid]) * w;
            __syncthreads();
            for (int off = 128; off; off >>= 1) {
                if (tid < off) red[tid] += red[tid + off];
                __syncthreads();
            }
            if (tid == 0) out[bb] = red[0] + cls_b[0];
            __syncthreads();
        }
    }
}

// =====================================================================
extern "C" void kernel_launch(void* const* d_in, const int* in_sizes, int n_in,
                              void* d_out, int out_size)
{
    (void)in_sizes; (void)n_in; (void)out_size;
    const float* x     = (const float*)d_in[0];
    const int*   ei    = (const int*)  d_in[1];
    const float* W1    = (const float*)d_in[2];
    const float* b1    = (const float*)d_in[3];
    const float* Wl    = (const float*)d_in[4];
    const float* Wr    = (const float*)d_in[5];
    const float* sb    = (const float*)d_in[6];
    const float* W2    = (const float*)d_in[7];
    const float* b2    = (const float*)d_in[8];
    const float* W_ih  = (const float*)d_in[9];
    const float* W_hh  = (const float*)d_in[10];
    const float* b_ih  = (const float*)d_in[11];
    const float* b_hh  = (const float*)d_in[12];
    const float* cls_W = (const float*)d_in[13];
    const float* cls_b = (const float*)d_in[14];
    float* out = (float*)d_out;

    const size_t smem = 55876 * sizeof(float);  // 223504 B
    cudaFuncSetAttribute(k_embed, cudaFuncAttributeMaxDynamicSharedMemorySize, (int)smem);

    k_embed<<<NG, NT, smem>>>(x, ei, W1, b1, Wl, Wr, sb, W2, b2);
    k_prep <<<NG, 256>>>(W_ih, b_ih, b_hh);
    k_lstm <<<64, 256>>>(W_hh, cls_W, cls_b, out);
}